// round 9
// baseline (speedup 1.0000x reference)
#include <cuda_runtime.h>

// RSLDS forward-backward smoother, B=8 T=1024 N=64 K=8.
// Outputs: forward | backward | gamma1 | gamma2 (concatenated in d_out).
//
// Blocked scan:
//   pass1: per-(chain,segment) 8x8 transfer-matrix products (linear)
//   pass2: sequential scan over segments -> boundary vectors (g_Vb, g_Rb)
//   pass3_fw: per-segment forward recursion -> unnormalized log2 alphas (g_fwu)
//   bwgamma: backward recursion fused with ALL posterior emission; the four
//            per-step normalizers (fw, bw, gamma1, gamma2-Z) are computed by a
//            SINGLE warp reduction — each ii lane-group reduces a different
//            quantity (the 4x replication is otherwise redundant).

#define FULLMASK 0xffffffffu
constexpr int B_ = 8, T_ = 1024, N_ = 64, K_ = 8;
constexpr int C_ = B_ * N_;          // 512 chains
constexpr int L_ = 32, S_ = 32;      // segment length, count
constexpr int TN = T_ * N_;
constexpr long long BTNK = (long long)B_ * T_ * N_ * K_;

__device__ float g_Q  [C_ * S_ * 64];  // segment transfer matrices (linear)
__device__ float g_Vb [C_ * S_ * 8];   // fw boundaries (linear, rescaled)
__device__ float g_Rb [C_ * S_ * 8];   // bw boundaries (linear, rescaled)
__device__ float g_fwu[BTNK];          // unnormalized log2 alpha'

__device__ __forceinline__ float ex2f(float x) {
    float y; asm("ex2.approx.ftz.f32 %0, %1;" : "=f"(y) : "f"(x)); return y;
}
__device__ __forceinline__ float lg2f(float x) {
    float y; asm("lg2.approx.f32 %0, %1;" : "=f"(y) : "f"(x)); return y;
}
__device__ __forceinline__ float rcpf(float x) {
    float y; asm("rcp.approx.ftz.f32 %0, %1;" : "=f"(y) : "f"(x)); return y;
}

#define L2E 1.4426950408889634f
#define LN2 0.6931471805599453f

// ---------------------------------------------------------------------------
// pass1: Q_s = M_te ... M_ts,  M_t[i,j] = exp(log_b_t[i] + log_a_t[i,j]).
// lane (i = lane>>2, q = lane&3) holds Q[i,2q], Q[i,2q+1]. Rescale every 4 steps.
// ---------------------------------------------------------------------------
__global__ void __launch_bounds__(128) pass1_kernel(
    const float* __restrict__ la, const float* __restrict__ lb)
{
    const int w    = blockIdx.x * 4 + (threadIdx.x >> 5);
    const int lane = threadIdx.x & 31;
    const int q    = lane & 3;
    const int i    = lane >> 2;
    const int c = w >> 5, s = w & 31;
    const int b = c >> 6, n = c & 63;
    const int tile0 = b * TN + n;

    const int ts = (s == 0) ? 1 : s * L_;
    const int te = s * L_ + L_ - 1;

    const float2* ap = (const float2*)la + (tile0 + ts * N_) * 32 + lane;
    const float*  bp = lb + (tile0 + ts * N_) * 8 + i;

    float Qx, Qy;
    {   // Q = M_ts
        float2 a2 = *ap;
        float  bi = *bp;
        Qx = ex2f((a2.x + bi) * L2E);
        Qy = ex2f((a2.y + bi) * L2E);
        ap += 32 * N_; bp += 8 * N_;
    }

    int cnt = 0;
    for (int t = ts + 1; t <= te; t++) {
        float2 a2 = *ap;
        float  bi = *bp;
        ap += 32 * N_; bp += 8 * N_;
        float mtx = ex2f((a2.x + bi) * L2E);   // mt[i,2q]
        float mty = ex2f((a2.y + bi) * L2E);   // mt[i,2q+1]

        float nx = 0.f, ny = 0.f;
        #pragma unroll
        for (int j2 = 0; j2 < 4; j2++) {
            float ma = __shfl_sync(FULLMASK, mtx, j2, 4);          // mt[i,2j2]
            float mb = __shfl_sync(FULLMASK, mty, j2, 4);          // mt[i,2j2+1]
            float qxa = __shfl_sync(FULLMASK, Qx, 8 * j2 + q);     // Q[2j2,2q]
            float qya = __shfl_sync(FULLMASK, Qy, 8 * j2 + q);     // Q[2j2,2q+1]
            float qxb = __shfl_sync(FULLMASK, Qx, 8 * j2 + 4 + q); // Q[2j2+1,2q]
            float qyb = __shfl_sync(FULLMASK, Qy, 8 * j2 + 4 + q); // Q[2j2+1,2q+1]
            nx = fmaf(ma, qxa, fmaf(mb, qxb, nx));
            ny = fmaf(ma, qya, fmaf(mb, qyb, ny));
        }
        Qx = nx; Qy = ny;
        if ((++cnt & 3) == 0 || t == te) {     // rescale every 4 steps + final
            float m = fmaxf(Qx, Qy);
            m = fmaxf(m, __shfl_xor_sync(FULLMASK, m, 1));
            m = fmaxf(m, __shfl_xor_sync(FULLMASK, m, 2));
            m = fmaxf(m, __shfl_xor_sync(FULLMASK, m, 4));
            m = fmaxf(m, __shfl_xor_sync(FULLMASK, m, 8));
            m = fmaxf(m, __shfl_xor_sync(FULLMASK, m, 16));
            float inv = rcpf(m);
            Qx *= inv; Qy *= inv;
        }
    }
    *(float2*)(g_Q + (size_t)(c * S_ + s) * 64 + lane * 2) = make_float2(Qx, Qy);
}

// ---------------------------------------------------------------------------
// pass2: sequential scan over segments. warp = (dir, chain).
// ---------------------------------------------------------------------------
__global__ void __launch_bounds__(128) pass2_kernel(
    const float* __restrict__ lb, const float* __restrict__ lz)
{
    const int w    = blockIdx.x * 4 + (threadIdx.x >> 5);
    const int lane = threadIdx.x & 31;
    const int q    = lane & 3;
    const int i    = lane >> 2;
    const bool is_bw = (w >= C_);
    const int c = is_bw ? w - C_ : w;
    const int b = c >> 6, n = c & 63;
    const int tile0 = b * TN + n;

    if (!is_bw) {
        float x = lz[n * 8 + i] + lb[tile0 * 8 + i];
        float m0 = x;
        m0 = fmaxf(m0, __shfl_xor_sync(FULLMASK, m0, 4));
        m0 = fmaxf(m0, __shfl_xor_sync(FULLMASK, m0, 8));
        m0 = fmaxf(m0, __shfl_xor_sync(FULLMASK, m0, 16));
        float vi = ex2f((x - m0) * L2E);       // v[i], replicated over q

        for (int s = 0; s <= 30; s++) {
            float2 Qr = *(const float2*)(g_Q + (size_t)(c * S_ + s) * 64 + lane * 2);
            float vx = __shfl_sync(FULLMASK, vi, 8 * q);
            float vy = __shfl_sync(FULLMASK, vi, 8 * q + 4);
            float p = fmaf(Qr.x, vx, Qr.y * vy);
            p += __shfl_xor_sync(FULLMASK, p, 1);
            p += __shfl_xor_sync(FULLMASK, p, 2);
            float m = p;
            m = fmaxf(m, __shfl_xor_sync(FULLMASK, m, 4));
            m = fmaxf(m, __shfl_xor_sync(FULLMASK, m, 8));
            m = fmaxf(m, __shfl_xor_sync(FULLMASK, m, 16));
            vi = p * rcpf(m);
            if (q == 0) g_Vb[(size_t)(c * S_ + s + 1) * 8 + i] = vi;
        }
    } else {
        float ri = 1.0f;
        for (int s = 31; s >= 1; s--) {
            float2 Qr = *(const float2*)(g_Q + (size_t)(c * S_ + s) * 64 + lane * 2);
            float pe = Qr.x * ri;
            float po = Qr.y * ri;
            pe += __shfl_xor_sync(FULLMASK, pe, 4);
            pe += __shfl_xor_sync(FULLMASK, pe, 8);
            pe += __shfl_xor_sync(FULLMASK, pe, 16);
            po += __shfl_xor_sync(FULLMASK, po, 4);
            po += __shfl_xor_sync(FULLMASK, po, 8);
            po += __shfl_xor_sync(FULLMASK, po, 16);
            float re = __shfl_sync(FULLMASK, pe, i >> 1);
            float ro = __shfl_sync(FULLMASK, po, i >> 1);
            float rn = (i & 1) ? ro : re;
            float m = fmaxf(pe, po);
            m = fmaxf(m, __shfl_xor_sync(FULLMASK, m, 1));
            m = fmaxf(m, __shfl_xor_sync(FULLMASK, m, 2));
            ri = rn * rcpf(m);
            if (q == 0) g_Rb[(size_t)(c * S_ + s) * 8 + i] = ri;
        }
    }
}

// ---------------------------------------------------------------------------
// pass3_fw: forward recursion per (chain,segment), emits unnormalized log2
// alphas into g_fwu. lane (i=rr, ii) handles j-pair 2ii,2ii+1 of row i.
// ---------------------------------------------------------------------------
__global__ void __launch_bounds__(128) pass3_fw_kernel(
    const float* __restrict__ la, const float* __restrict__ lb,
    const float* __restrict__ lz)
{
    const int w    = blockIdx.x * 4 + (threadIdx.x >> 5);
    const int lane = threadIdx.x & 31;
    const int ii   = lane & 3;
    const int rr   = lane >> 2;
    const int c = w >> 5, s = w & 31;
    const int b = c >> 6, n = c & 63;
    const int tile0 = b * TN + n;
    const int sel0 = ii * 8, sel1 = ii * 8 + 4;

    float prev;
    int t0;
    if (s == 0) {
        prev = (lz[n * 8 + rr] + lb[tile0 * 8 + rr]) * L2E;
        if (ii == 0) g_fwu[tile0 * 8 + rr] = prev;
        t0 = 1;
    } else {
        prev = lg2f(g_Vb[(c * S_ + s) * 8 + rr]);
        t0 = s * L_;
    }
    const int t1 = s * L_ + L_ - 1;

    const float2* ap = (const float2*)la + (tile0 + t0 * N_) * 32 + lane;
    const float*  bp = lb + (tile0 + t0 * N_) * 8 + rr;
    float*        op = g_fwu + (tile0 + t0 * N_) * 8 + rr;

    for (int t = t0; t <= t1; t++) {
        float2 av = *ap;
        float  bv = *bp;
        ap += 32 * N_; bp += 8 * N_;
        float p0 = __shfl_sync(FULLMASK, prev, sel0);
        float p1 = __shfl_sync(FULLMASK, prev, sel1);
        float u0 = __shfl_sync(FULLMASK, prev, 0);
        float e = ex2f(fmaf(av.x, L2E, p0 - u0))
                + ex2f(fmaf(av.y, L2E, p1 - u0));
        e += __shfl_xor_sync(FULLMASK, e, 1);
        e += __shfl_xor_sync(FULLMASK, e, 2);
        float uu = fmaf(bv, L2E, lg2f(e));
        prev = uu;
        if (ii == 0) *op = uu;
        op += 8 * N_;
    }
}

// ---------------------------------------------------------------------------
// bwgamma: backward recursion + all output emission, ONE reduction per step.
// Warp = (chain, segment). lane (j=rr, ii) handles i-pair 2ii,2ii+1 of col j.
// Step computing beta_t emits outputs for time t+1; a tail step emits t = s*L.
// Unified reduction: ii-group 0 -> bw norm, 1 -> fw norm, 2 -> gamma1 norm,
// 3 -> gamma2 partition Z (= sum_j e_j * 2^fwu_t[j], reusing recursion's e).
// ---------------------------------------------------------------------------
__global__ void __launch_bounds__(128) bwgamma_kernel(
    const float* __restrict__ la, const float* __restrict__ lb,
    float* __restrict__ fw, float* __restrict__ bwo,
    float* __restrict__ g1, float* __restrict__ g2)
{
    const int w    = blockIdx.x * 4 + (threadIdx.x >> 5);
    const int lane = threadIdx.x & 31;
    const int ii   = lane & 3;
    const int rr   = lane >> 2;
    const int c = w >> 5, s = w & 31;
    const int b = c >> 6, n = c & 63;
    const int tile0 = b * TN + n;
    const int sel0 = ii * 8, sel1 = ii * 8 + 4;
    const int te = s * L_ + L_ - 1;

    // beta_{te} (anchored log2) and fwu[te]
    float prev  = (s == 31) ? 0.0f : lg2f(g_Rb[(c * S_ + s + 1) * 8 + rr]);
    float fprev = g_fwu[(tile0 + te * N_) * 8 + rr];

    const float*  cp  = la + (tile0 + te * N_) * 64 + ii * 16 + rr;
    const float2* bp2 = (const float2*)lb + (tile0 + te * N_) * 4 + ii;
    const float*  fp  = g_fwu + (tile0 + (te - 1) * N_) * 8 + rr;
    int ob  = (tile0 + te * N_) * 8 + rr;       // fw/bw/g1 (pred ii==0)
    int g2b = (tile0 + te * N_) * 64;           // gamma2 tile base

    const bool top = (s == 31);

    for (int t = te - 1; t >= s * L_; t--) {
        float  c0 = cp[0];            // la_{t+1}[2ii][j]
        float  c1 = cp[8];            // la_{t+1}[2ii+1][j]
        float2 bv = *bp2;             // lb_{t+1}[2ii], [2ii+1]
        float fcur = *fp;             // fwu[t]
        cp -= 64 * N_; bp2 -= 4 * N_; fp -= 8 * N_;

        // recursion core (beta_{t+1} -> beta_t)
        float p0 = __shfl_sync(FULLMASK, prev, sel0);
        float p1 = __shfl_sync(FULLMASK, prev, sel1);
        float u0 = __shfl_sync(FULLMASK, prev, 0);
        float a0 = fmaf(c0 + bv.x, L2E, p0 - u0);
        float a1 = fmaf(c1 + bv.y, L2E, p1 - u0);
        float e  = ex2f(a0) + ex2f(a1);
        e += __shfl_xor_sync(FULLMASK, e, 1);
        e += __shfl_xor_sync(FULLMASK, e, 2);   // e(rr) = sum over i, repl. over ii

        // ---- unified emission reduction for time t+1 ----
        float val = (ii == 0) ? prev
                  : (ii == 1) ? fprev
                  : (ii == 2) ? (fprev + prev) : fcur;
        float ee = ex2f(val);
        if (ii == 3) ee *= e;                   // gamma2 Z terms: e_j * 2^fwu_t[j]
        ee += __shfl_xor_sync(FULLMASK, ee, 4);
        ee += __shfl_xor_sync(FULLMASK, ee, 8);
        ee += __shfl_xor_sync(FULLMASK, ee, 16);
        float lgE = lg2f(ee);                   // function of ii only
        float lgF = __shfl_sync(FULLMASK, lgE, 1);   // fw normalizer
        float lgG = __shfl_sync(FULLMASK, lgE, 2);   // gamma1 normalizer
        float lgZ = __shfl_sync(FULLMASK, lgE, 3);   // gamma2 normalizer

        // fw/bw/g1 (valid at ii==0 lanes: lgE there is the bw normalizer)
        float bwout = (top && t == te - 1) ? 0.0f : (prev - lgE) * LN2;
        float fwout = (fprev - lgF) * LN2;
        float g1out = (fprev + prev - lgG) * LN2;
        if (ii == 0) { fw[ob] = fwout; bwo[ob] = bwout; g1[ob] = g1out; }

        // gamma2[t+1][i][j] = (a_i + fwu_t[j] - lgZ) * LN2
        float tt2 = (fcur - lgZ) * LN2;
        g2[g2b + 16 * ii + rr]     = fmaf(a0, LN2, tt2);
        g2[g2b + 16 * ii + 8 + rr] = fmaf(a1, LN2, tt2);

        // finish recursion
        prev  = lg2f(e);
        fprev = fcur;
        ob -= 8 * N_; g2b -= 64 * N_;
    }

    // ---- tail emission for time t = s*L (prev = beta_{sL}, fprev = fwu[sL]) ----
    {
        float a0t = 0.f, a1t = 0.f, et = 1.0f, fct = 0.f;
        if (s != 0) {
            const float* cpe = la + (tile0 + s * L_ * N_) * 64 + ii * 16 + rr;
            float  c0 = cpe[0];
            float  c1 = cpe[8];
            float2 bv = *((const float2*)lb + (tile0 + s * L_ * N_) * 4 + ii);
            fct = lg2f(g_Vb[(c * S_ + s) * 8 + rr]);     // fwu[sL-1] (shifted)
            float p0 = __shfl_sync(FULLMASK, prev, sel0);
            float p1 = __shfl_sync(FULLMASK, prev, sel1);
            float u0 = __shfl_sync(FULLMASK, prev, 0);
            a0t = fmaf(c0 + bv.x, L2E, p0 - u0);
            a1t = fmaf(c1 + bv.y, L2E, p1 - u0);
            et  = ex2f(a0t) + ex2f(a1t);
            et += __shfl_xor_sync(FULLMASK, et, 1);
            et += __shfl_xor_sync(FULLMASK, et, 2);
        }
        float val = (ii == 0) ? prev
                  : (ii == 1) ? fprev
                  : (ii == 2) ? (fprev + prev) : fct;
        float ee = ex2f(val);
        if (ii == 3) ee *= et;
        ee += __shfl_xor_sync(FULLMASK, ee, 4);
        ee += __shfl_xor_sync(FULLMASK, ee, 8);
        ee += __shfl_xor_sync(FULLMASK, ee, 16);
        float lgE = lg2f(ee);
        float lgF = __shfl_sync(FULLMASK, lgE, 1);
        float lgG = __shfl_sync(FULLMASK, lgE, 2);
        float lgZ = __shfl_sync(FULLMASK, lgE, 3);

        float bwout = (prev - lgE) * LN2;
        float fwout = (fprev - lgF) * LN2;
        float g1out = (fprev + prev - lgG) * LN2;
        if (ii == 0) { fw[ob] = fwout; bwo[ob] = bwout; g1[ob] = g1out; }

        if (s == 0) {                            // gamma2[0] = zeros
            g2[g2b + 16 * ii + rr]     = 0.0f;
            g2[g2b + 16 * ii + 8 + rr] = 0.0f;
        } else {
            float tt2 = (fct - lgZ) * LN2;
            g2[g2b + 16 * ii + rr]     = fmaf(a0t, LN2, tt2);
            g2[g2b + 16 * ii + 8 + rr] = fmaf(a1t, LN2, tt2);
        }
    }
}

extern "C" void kernel_launch(void* const* d_in, const int* in_sizes, int n_in,
                              void* d_out, int out_size) {
    const float* la = (const float*)d_in[0];   // log_a  (B,T,N,K,K)
    const float* lb = (const float*)d_in[1];   // log_b  (B,T,N,K)
    const float* lz = (const float*)d_in[2];   // logprob_z1 (N,K)

    float* out = (float*)d_out;
    float* fw = out;
    float* bw = fw + BTNK;
    float* g1 = bw + BTNK;
    float* g2 = g1 + BTNK;

    pass1_kernel<<<(C_ * S_) / 4, 128>>>(la, lb);          // 16384 warps
    pass2_kernel<<<(2 * C_) / 4, 128>>>(lb, lz);           // 1024 warps
    pass3_fw_kernel<<<(C_ * S_) / 4, 128>>>(la, lb, lz);   // 16384 warps
    bwgamma_kernel<<<(C_ * S_) / 4, 128>>>(la, lb, fw, bw, g1, g2);
}

// round 10
// speedup vs baseline: 1.1313x; 1.1313x over previous
#include <cuda_runtime.h>

// RSLDS forward-backward smoother, B=8 T=1024 N=64 K=8.
// Outputs: forward | backward | gamma1 | gamma2 (concatenated in d_out).
//
// Blocked scan:
//   pass1: per-(chain,segment) 8x8 transfer-matrix products (linear)
//   pass2: sequential scan over segments -> boundary vectors (g_Vb, g_Rb)
//   pass3_fw: per-segment forward recursion -> unnormalized log2 alphas (g_fwu)
//   bwgamma: backward recursion + ALL posterior emission, one unified warp
//            reduction per step (ii-groups reduce bw/fw/g1/g2-Z respectively).
// R10: depth-2 register double-buffer prefetch in all three scan loops —
// loads are issued >=2 iterations before first consumption (latency was the
// binding constraint per R9 ncu: issue 47%, DRAM 39%, neither saturated).

#define FULLMASK 0xffffffffu
constexpr int B_ = 8, T_ = 1024, N_ = 64, K_ = 8;
constexpr int C_ = B_ * N_;          // 512 chains
constexpr int L_ = 32, S_ = 32;      // segment length, count
constexpr int TN = T_ * N_;
constexpr long long BTNK = (long long)B_ * T_ * N_ * K_;

__device__ float g_Q  [C_ * S_ * 64];  // segment transfer matrices (linear)
__device__ float g_Vb [C_ * S_ * 8];   // fw boundaries (linear, rescaled)
__device__ float g_Rb [C_ * S_ * 8];   // bw boundaries (linear, rescaled)
__device__ float g_fwu[BTNK];          // unnormalized log2 alpha'

__device__ __forceinline__ float ex2f(float x) {
    float y; asm("ex2.approx.ftz.f32 %0, %1;" : "=f"(y) : "f"(x)); return y;
}
__device__ __forceinline__ float lg2f(float x) {
    float y; asm("lg2.approx.f32 %0, %1;" : "=f"(y) : "f"(x)); return y;
}
__device__ __forceinline__ float rcpf(float x) {
    float y; asm("rcp.approx.ftz.f32 %0, %1;" : "=f"(y) : "f"(x)); return y;
}

#define L2E 1.4426950408889634f
#define LN2 0.6931471805599453f

// ---------------------------------------------------------------------------
// pass1: Q_s = M_te ... M_ts,  M_t[i,j] = exp(log_b_t[i] + log_a_t[i,j]).
// lane (i = lane>>2, q = lane&3) holds Q[i,2q], Q[i,2q+1].
// ---------------------------------------------------------------------------
__global__ void __launch_bounds__(128) pass1_kernel(
    const float* __restrict__ la, const float* __restrict__ lb)
{
    const int w    = blockIdx.x * 4 + (threadIdx.x >> 5);
    const int lane = threadIdx.x & 31;
    const int q    = lane & 3;
    const int i    = lane >> 2;
    const int c = w >> 5, s = w & 31;
    const int b = c >> 6, n = c & 63;
    const int tile0 = b * TN + n;

    const int ts = (s == 0) ? 1 : s * L_;
    const int te = s * L_ + L_ - 1;
    const int cnt = te - ts;                 // multiply steps: 30 or 31

    const float2* ap = (const float2*)la + (tile0 + ts * N_) * 32 + lane;
    const float*  bp = lb + (tile0 + ts * N_) * 8 + i;

    float Qx, Qy;
    {   // Q = M_ts
        float2 a2 = *ap;
        float  bi = *bp;
        Qx = ex2f((a2.x + bi) * L2E);
        Qy = ex2f((a2.y + bi) * L2E);
        ap += 32 * N_; bp += 8 * N_;
    }

    // depth-2 prefetch buffers (cnt >= 30 always)
    float2 a2x = ap[0];        float bix = bp[0];
    float2 a2y = ap[32 * N_];  float biy = bp[8 * N_];
    ap += 64 * N_; bp += 16 * N_;

    int rcnt = 0;
    auto mstep = [&](float2 a2, float bi) {
        float mtx = ex2f((a2.x + bi) * L2E);   // mt[i,2q]
        float mty = ex2f((a2.y + bi) * L2E);   // mt[i,2q+1]
        float nx = 0.f, ny = 0.f;
        #pragma unroll
        for (int j2 = 0; j2 < 4; j2++) {
            float ma = __shfl_sync(FULLMASK, mtx, j2, 4);
            float mb = __shfl_sync(FULLMASK, mty, j2, 4);
            float qxa = __shfl_sync(FULLMASK, Qx, 8 * j2 + q);
            float qya = __shfl_sync(FULLMASK, Qy, 8 * j2 + q);
            float qxb = __shfl_sync(FULLMASK, Qx, 8 * j2 + 4 + q);
            float qyb = __shfl_sync(FULLMASK, Qy, 8 * j2 + 4 + q);
            nx = fmaf(ma, qxa, fmaf(mb, qxb, nx));
            ny = fmaf(ma, qya, fmaf(mb, qyb, ny));
        }
        Qx = nx; Qy = ny;
        ++rcnt;
        if ((rcnt & 3) == 0 || rcnt == cnt) {
            float m = fmaxf(Qx, Qy);
            m = fmaxf(m, __shfl_xor_sync(FULLMASK, m, 1));
            m = fmaxf(m, __shfl_xor_sync(FULLMASK, m, 2));
            m = fmaxf(m, __shfl_xor_sync(FULLMASK, m, 4));
            m = fmaxf(m, __shfl_xor_sync(FULLMASK, m, 8));
            m = fmaxf(m, __shfl_xor_sync(FULLMASK, m, 16));
            float inv = rcpf(m);
            Qx *= inv; Qy *= inv;
        }
    };

    for (int u = 0; u + 2 <= cnt; u += 2) {
        float2 a = a2x; float bb = bix;
        if (u + 2 < cnt) { a2x = *ap; bix = *bp; ap += 32 * N_; bp += 8 * N_; }
        mstep(a, bb);
        a = a2y; bb = biy;
        if (u + 3 < cnt) { a2y = *ap; biy = *bp; ap += 32 * N_; bp += 8 * N_; }
        mstep(a, bb);
    }
    if (cnt & 1) mstep(a2x, bix);

    *(float2*)(g_Q + (size_t)(c * S_ + s) * 64 + lane * 2) = make_float2(Qx, Qy);
}

// ---------------------------------------------------------------------------
// pass2: sequential scan over segments. warp = (dir, chain).
// ---------------------------------------------------------------------------
__global__ void __launch_bounds__(128) pass2_kernel(
    const float* __restrict__ lb, const float* __restrict__ lz)
{
    const int w    = blockIdx.x * 4 + (threadIdx.x >> 5);
    const int lane = threadIdx.x & 31;
    const int q    = lane & 3;
    const int i    = lane >> 2;
    const bool is_bw = (w >= C_);
    const int c = is_bw ? w - C_ : w;
    const int b = c >> 6, n = c & 63;
    const int tile0 = b * TN + n;

    if (!is_bw) {
        float x = lz[n * 8 + i] + lb[tile0 * 8 + i];
        float m0 = x;
        m0 = fmaxf(m0, __shfl_xor_sync(FULLMASK, m0, 4));
        m0 = fmaxf(m0, __shfl_xor_sync(FULLMASK, m0, 8));
        m0 = fmaxf(m0, __shfl_xor_sync(FULLMASK, m0, 16));
        float vi = ex2f((x - m0) * L2E);       // v[i], replicated over q

        for (int s = 0; s <= 30; s++) {
            float2 Qr = *(const float2*)(g_Q + (size_t)(c * S_ + s) * 64 + lane * 2);
            float vx = __shfl_sync(FULLMASK, vi, 8 * q);
            float vy = __shfl_sync(FULLMASK, vi, 8 * q + 4);
            float p = fmaf(Qr.x, vx, Qr.y * vy);
            p += __shfl_xor_sync(FULLMASK, p, 1);
            p += __shfl_xor_sync(FULLMASK, p, 2);
            float m = p;
            m = fmaxf(m, __shfl_xor_sync(FULLMASK, m, 4));
            m = fmaxf(m, __shfl_xor_sync(FULLMASK, m, 8));
            m = fmaxf(m, __shfl_xor_sync(FULLMASK, m, 16));
            vi = p * rcpf(m);
            if (q == 0) g_Vb[(size_t)(c * S_ + s + 1) * 8 + i] = vi;
        }
    } else {
        float ri = 1.0f;
        for (int s = 31; s >= 1; s--) {
            float2 Qr = *(const float2*)(g_Q + (size_t)(c * S_ + s) * 64 + lane * 2);
            float pe = Qr.x * ri;
            float po = Qr.y * ri;
            pe += __shfl_xor_sync(FULLMASK, pe, 4);
            pe += __shfl_xor_sync(FULLMASK, pe, 8);
            pe += __shfl_xor_sync(FULLMASK, pe, 16);
            po += __shfl_xor_sync(FULLMASK, po, 4);
            po += __shfl_xor_sync(FULLMASK, po, 8);
            po += __shfl_xor_sync(FULLMASK, po, 16);
            float re = __shfl_sync(FULLMASK, pe, i >> 1);
            float ro = __shfl_sync(FULLMASK, po, i >> 1);
            float rn = (i & 1) ? ro : re;
            float m = fmaxf(pe, po);
            m = fmaxf(m, __shfl_xor_sync(FULLMASK, m, 1));
            m = fmaxf(m, __shfl_xor_sync(FULLMASK, m, 2));
            ri = rn * rcpf(m);
            if (q == 0) g_Rb[(size_t)(c * S_ + s) * 8 + i] = ri;
        }
    }
}

// ---------------------------------------------------------------------------
// pass3_fw: forward recursion per (chain,segment) -> g_fwu (unnormalized log2).
// lane (i=rr, ii) handles j-pair 2ii,2ii+1 of row i. Depth-2 prefetch.
// ---------------------------------------------------------------------------
__global__ void __launch_bounds__(128) pass3_fw_kernel(
    const float* __restrict__ la, const float* __restrict__ lb,
    const float* __restrict__ lz)
{
    const int w    = blockIdx.x * 4 + (threadIdx.x >> 5);
    const int lane = threadIdx.x & 31;
    const int ii   = lane & 3;
    const int rr   = lane >> 2;
    const int c = w >> 5, s = w & 31;
    const int b = c >> 6, n = c & 63;
    const int tile0 = b * TN + n;
    const int sel0 = ii * 8, sel1 = ii * 8 + 4;

    float prev;
    int t0;
    if (s == 0) {
        prev = (lz[n * 8 + rr] + lb[tile0 * 8 + rr]) * L2E;
        if (ii == 0) g_fwu[tile0 * 8 + rr] = prev;
        t0 = 1;
    } else {
        prev = lg2f(g_Vb[(c * S_ + s) * 8 + rr]);
        t0 = s * L_;
    }
    const int cnt = s * L_ + L_ - t0;        // 31 or 32

    const float2* ap = (const float2*)la + (tile0 + t0 * N_) * 32 + lane;
    const float*  bp = lb + (tile0 + t0 * N_) * 8 + rr;
    float*        op = g_fwu + (tile0 + t0 * N_) * 8 + rr;

    float2 avx = ap[0];       float bvx = bp[0];
    float2 avy = ap[32 * N_]; float bvy = bp[8 * N_];
    ap += 64 * N_; bp += 16 * N_;

    auto fstep = [&](float2 av, float bv) {
        float p0 = __shfl_sync(FULLMASK, prev, sel0);
        float p1 = __shfl_sync(FULLMASK, prev, sel1);
        float u0 = __shfl_sync(FULLMASK, prev, 0);
        float e = ex2f(fmaf(av.x, L2E, p0 - u0))
                + ex2f(fmaf(av.y, L2E, p1 - u0));
        e += __shfl_xor_sync(FULLMASK, e, 1);
        e += __shfl_xor_sync(FULLMASK, e, 2);
        float uu = fmaf(bv, L2E, lg2f(e));
        prev = uu;
        if (ii == 0) *op = uu;
        op += 8 * N_;
    };

    for (int u = 0; u + 2 <= cnt; u += 2) {
        float2 a = avx; float bb = bvx;
        if (u + 2 < cnt) { avx = *ap; bvx = *bp; ap += 32 * N_; bp += 8 * N_; }
        fstep(a, bb);
        a = avy; bb = bvy;
        if (u + 3 < cnt) { avy = *ap; bvy = *bp; ap += 32 * N_; bp += 8 * N_; }
        fstep(a, bb);
    }
    if (cnt & 1) fstep(avx, bvx);
}

// ---------------------------------------------------------------------------
// bwgamma: backward recursion + all output emission, ONE reduction per step.
// Warp = (chain, segment). lane (j=rr, ii) handles i-pair 2ii,2ii+1 of col j.
// Step computing beta_t emits outputs for time t+1; a tail step emits t = s*L.
// Depth-2 register prefetch of la/lb/fwu.
// ---------------------------------------------------------------------------
__global__ void __launch_bounds__(128) bwgamma_kernel(
    const float* __restrict__ la, const float* __restrict__ lb,
    float* __restrict__ fw, float* __restrict__ bwo,
    float* __restrict__ g1, float* __restrict__ g2)
{
    const int w    = blockIdx.x * 4 + (threadIdx.x >> 5);
    const int lane = threadIdx.x & 31;
    const int ii   = lane & 3;
    const int rr   = lane >> 2;
    const int c = w >> 5, s = w & 31;
    const int b = c >> 6, n = c & 63;
    const int tile0 = b * TN + n;
    const int sel0 = ii * 8, sel1 = ii * 8 + 4;
    const int te = s * L_ + L_ - 1;
    const bool top = (s == 31);

    float prev  = top ? 0.0f : lg2f(g_Rb[(c * S_ + s + 1) * 8 + rr]);
    float fprev = g_fwu[(tile0 + te * N_) * 8 + rr];

    const float*  cp  = la + (tile0 + te * N_) * 64 + ii * 16 + rr;
    const float2* bp2 = (const float2*)lb + (tile0 + te * N_) * 4 + ii;
    const float*  fp  = g_fwu + (tile0 + (te - 1) * N_) * 8 + rr;
    int ob  = (tile0 + te * N_) * 8 + rr;       // fw/bw/g1 (pred ii==0)
    int g2b = (tile0 + te * N_) * 64;           // gamma2 tile base

    // depth-2 prefetch (31 iterations always)
    float c0x = cp[0], c1x = cp[8];
    float2 bvx = bp2[0];
    float fcx = fp[0];
    float c0y = cp[-64 * N_], c1y = cp[-64 * N_ + 8];
    float2 bvy = bp2[-4 * N_];
    float fcy = fp[-8 * N_];
    cp -= 128 * N_; bp2 -= 8 * N_; fp -= 16 * N_;

    auto step = [&](float c0, float c1, float2 bv, float fcur, bool first) {
        // recursion core (beta_{t+1} -> beta_t)
        float p0 = __shfl_sync(FULLMASK, prev, sel0);
        float p1 = __shfl_sync(FULLMASK, prev, sel1);
        float u0 = __shfl_sync(FULLMASK, prev, 0);
        float a0 = fmaf(c0 + bv.x, L2E, p0 - u0);
        float a1 = fmaf(c1 + bv.y, L2E, p1 - u0);
        float e  = ex2f(a0) + ex2f(a1);
        e += __shfl_xor_sync(FULLMASK, e, 1);
        e += __shfl_xor_sync(FULLMASK, e, 2);   // e(rr) = sum over i

        // unified emission reduction for time t+1
        float val = (ii == 0) ? prev
                  : (ii == 1) ? fprev
                  : (ii == 2) ? (fprev + prev) : fcur;
        float ee = ex2f(val);
        if (ii == 3) ee *= e;                   // gamma2 Z terms
        ee += __shfl_xor_sync(FULLMASK, ee, 4);
        ee += __shfl_xor_sync(FULLMASK, ee, 8);
        ee += __shfl_xor_sync(FULLMASK, ee, 16);
        float lgE = lg2f(ee);                   // function of ii only
        float lgF = __shfl_sync(FULLMASK, lgE, 1);
        float lgG = __shfl_sync(FULLMASK, lgE, 2);
        float lgZ = __shfl_sync(FULLMASK, lgE, 3);

        float bwout = (top && first) ? 0.0f : (prev - lgE) * LN2;
        float fwout = (fprev - lgF) * LN2;
        float g1out = (fprev + prev - lgG) * LN2;
        if (ii == 0) { fw[ob] = fwout; bwo[ob] = bwout; g1[ob] = g1out; }

        float tt2 = (fcur - lgZ) * LN2;
        g2[g2b + 16 * ii + rr]     = fmaf(a0, LN2, tt2);
        g2[g2b + 16 * ii + 8 + rr] = fmaf(a1, LN2, tt2);

        prev  = lg2f(e);
        fprev = fcur;
        ob -= 8 * N_; g2b -= 64 * N_;
    };

    for (int u = 0; u + 2 <= 31; u += 2) {
        {
            float c0 = c0x, c1 = c1x; float2 bv = bvx; float fc = fcx;
            if (u + 2 < 31) {
                c0x = cp[0]; c1x = cp[8]; bvx = bp2[0]; fcx = fp[0];
                cp -= 64 * N_; bp2 -= 4 * N_; fp -= 8 * N_;
            }
            step(c0, c1, bv, fc, u == 0);
        }
        {
            float c0 = c0y, c1 = c1y; float2 bv = bvy; float fc = fcy;
            if (u + 3 < 31) {
                c0y = cp[0]; c1y = cp[8]; bvy = bp2[0]; fcy = fp[0];
                cp -= 64 * N_; bp2 -= 4 * N_; fp -= 8 * N_;
            }
            step(c0, c1, bv, fc, false);
        }
    }
    step(c0x, c1x, bvx, fcx, false);           // iteration 30 (odd leftover)

    // ---- tail emission for time t = s*L (prev = beta_{sL}, fprev = fwu[sL]) ----
    {
        float a0t = 0.f, a1t = 0.f, et = 1.0f, fct = 0.f;
        if (s != 0) {
            const float* cpe = la + (tile0 + s * L_ * N_) * 64 + ii * 16 + rr;
            float  c0 = cpe[0];
            float  c1 = cpe[8];
            float2 bv = *((const float2*)lb + (tile0 + s * L_ * N_) * 4 + ii);
            fct = lg2f(g_Vb[(c * S_ + s) * 8 + rr]);     // fwu[sL-1] (shifted)
            float p0 = __shfl_sync(FULLMASK, prev, sel0);
            float p1 = __shfl_sync(FULLMASK, prev, sel1);
            float u0 = __shfl_sync(FULLMASK, prev, 0);
            a0t = fmaf(c0 + bv.x, L2E, p0 - u0);
            a1t = fmaf(c1 + bv.y, L2E, p1 - u0);
            et  = ex2f(a0t) + ex2f(a1t);
            et += __shfl_xor_sync(FULLMASK, et, 1);
            et += __shfl_xor_sync(FULLMASK, et, 2);
        }
        float val = (ii == 0) ? prev
                  : (ii == 1) ? fprev
                  : (ii == 2) ? (fprev + prev) : fct;
        float ee = ex2f(val);
        if (ii == 3) ee *= et;
        ee += __shfl_xor_sync(FULLMASK, ee, 4);
        ee += __shfl_xor_sync(FULLMASK, ee, 8);
        ee += __shfl_xor_sync(FULLMASK, ee, 16);
        float lgE = lg2f(ee);
        float lgF = __shfl_sync(FULLMASK, lgE, 1);
        float lgG = __shfl_sync(FULLMASK, lgE, 2);
        float lgZ = __shfl_sync(FULLMASK, lgE, 3);

        float bwout = (prev - lgE) * LN2;
        float fwout = (fprev - lgF) * LN2;
        float g1out = (fprev + prev - lgG) * LN2;
        if (ii == 0) { fw[ob] = fwout; bwo[ob] = bwout; g1[ob] = g1out; }

        if (s == 0) {                            // gamma2[0] = zeros
            g2[g2b + 16 * ii + rr]     = 0.0f;
            g2[g2b + 16 * ii + 8 + rr] = 0.0f;
        } else {
            float tt2 = (fct - lgZ) * LN2;
            g2[g2b + 16 * ii + rr]     = fmaf(a0t, LN2, tt2);
            g2[g2b + 16 * ii + 8 + rr] = fmaf(a1t, LN2, tt2);
        }
    }
}

extern "C" void kernel_launch(void* const* d_in, const int* in_sizes, int n_in,
                              void* d_out, int out_size) {
    const float* la = (const float*)d_in[0];   // log_a  (B,T,N,K,K)
    const float* lb = (const float*)d_in[1];   // log_b  (B,T,N,K)
    const float* lz = (const float*)d_in[2];   // logprob_z1 (N,K)

    float* out = (float*)d_out;
    float* fw = out;
    float* bw = fw + BTNK;
    float* g1 = bw + BTNK;
    float* g2 = g1 + BTNK;

    pass1_kernel<<<(C_ * S_) / 4, 128>>>(la, lb);          // 16384 warps
    pass2_kernel<<<(2 * C_) / 4, 128>>>(lb, lz);           // 1024 warps
    pass3_fw_kernel<<<(C_ * S_) / 4, 128>>>(la, lb, lz);   // 16384 warps
    bwgamma_kernel<<<(C_ * S_) / 4, 128>>>(la, lb, fw, bw, g1, g2);
}

// round 11
// speedup vs baseline: 1.1770x; 1.0405x over previous
#include <cuda_runtime.h>

// RSLDS forward-backward smoother, B=8 T=1024 N=64 K=8.
// Outputs: forward | backward | gamma1 | gamma2 (concatenated in d_out).
//
// Blocked scan:
//   pass1: per-(chain,segment) 8x8 transfer-matrix products (linear).
//          R11: each lane LOADS its half-row of M_t directly (float4) and
//          butterflies the other half (4 shfl) instead of 8 broadcast shfl:
//          24 -> 20 shuffles/step (pass1 is SHFL-pipe bound).
//   pass2: sequential scan over segments -> boundary vectors (g_Vb, g_Rb)
//   pass3_fw: per-segment forward recursion -> unnormalized log2 alphas (g_fwu)
//   bwgamma: backward recursion + all posterior emission; unified per-ii
//          reduction, R11: each ii-group stores ITS OWN output (bw/fw/g1) —
//          no normalizer distribution shuffles (only gamma2's lgZ fetch).

#define FULLMASK 0xffffffffu
constexpr int B_ = 8, T_ = 1024, N_ = 64, K_ = 8;
constexpr int C_ = B_ * N_;          // 512 chains
constexpr int L_ = 32, S_ = 32;      // segment length, count
constexpr int TN = T_ * N_;
constexpr long long BTNK = (long long)B_ * T_ * N_ * K_;

__device__ float g_Q  [C_ * S_ * 64];  // segment transfer matrices (linear)
__device__ float g_Vb [C_ * S_ * 8];   // fw boundaries (linear, rescaled)
__device__ float g_Rb [C_ * S_ * 8];   // bw boundaries (linear, rescaled)
__device__ float g_fwu[BTNK];          // unnormalized log2 alpha'

__device__ __forceinline__ float ex2f(float x) {
    float y; asm("ex2.approx.ftz.f32 %0, %1;" : "=f"(y) : "f"(x)); return y;
}
__device__ __forceinline__ float lg2f(float x) {
    float y; asm("lg2.approx.f32 %0, %1;" : "=f"(y) : "f"(x)); return y;
}
__device__ __forceinline__ float rcpf(float x) {
    float y; asm("rcp.approx.ftz.f32 %0, %1;" : "=f"(y) : "f"(x)); return y;
}

#define L2E 1.4426950408889634f
#define LN2 0.6931471805599453f

// ---------------------------------------------------------------------------
// pass1: Q_s = M_te ... M_ts,  M_t[i,j] = exp(log_b_t[i] + log_a_t[i,j]).
// lane (i = lane>>2, q = lane&3) holds Q[i,2q], Q[i,2q+1].
// Lane loads M row-half [4h..4h+4) with h = q>>1; butterfly xor 2 for the rest.
// ---------------------------------------------------------------------------
__global__ void __launch_bounds__(128) pass1_kernel(
    const float* __restrict__ la, const float* __restrict__ lb)
{
    const int w    = blockIdx.x * 4 + (threadIdx.x >> 5);
    const int lane = threadIdx.x & 31;
    const int q    = lane & 3;
    const int i    = lane >> 2;
    const int h    = q >> 1;
    const int c = w >> 5, s = w & 31;
    const int b = c >> 6, n = c & 63;
    const int tile0 = b * TN + n;

    const int srcL = 16 * h + q;          // Q-gather lanes for local half
    const int srcR = 16 - 16 * h + q;     // and remote half

    const int ts = (s == 0) ? 1 : s * L_;
    const int te = s * L_ + L_ - 1;
    const int cnt = te - ts;              // multiply steps: 30 or 31

    const float4* ap = (const float4*)(la + (size_t)(tile0 + ts * N_) * 64) + i * 2 + h;
    const float*  bp = lb + (tile0 + ts * N_) * 8 + i;

    float Qx, Qy;
    {   // Q = M_ts
        float4 a4 = *ap;
        float  biL = (*bp) * L2E;
        float ax = (q & 1) ? a4.z : a4.x;
        float ay = (q & 1) ? a4.w : a4.y;
        Qx = ex2f(fmaf(ax, L2E, biL));
        Qy = ex2f(fmaf(ay, L2E, biL));
        ap += 16 * N_; bp += 8 * N_;
    }

    // depth-2 prefetch buffers (cnt >= 30 always)
    float4 a4x = ap[0];        float bix = bp[0];
    float4 a4y = ap[16 * N_];  float biy = bp[8 * N_];
    ap += 32 * N_; bp += 16 * N_;

    int rcnt = 0;
    auto mstep = [&](float4 a4, float bi) {
        float biL = bi * L2E;
        float m0 = ex2f(fmaf(a4.x, L2E, biL));
        float m1 = ex2f(fmaf(a4.y, L2E, biL));
        float m2 = ex2f(fmaf(a4.z, L2E, biL));
        float m3 = ex2f(fmaf(a4.w, L2E, biL));
        float o0 = __shfl_xor_sync(FULLMASK, m0, 2);
        float o1 = __shfl_xor_sync(FULLMASK, m1, 2);
        float o2 = __shfl_xor_sync(FULLMASK, m2, 2);
        float o3 = __shfl_xor_sync(FULLMASK, m3, 2);

        float nx = 0.f, ny = 0.f;
        {   // local half: l = 4h + cc
            float qx, qy;
            qx = __shfl_sync(FULLMASK, Qx, srcL);      qy = __shfl_sync(FULLMASK, Qy, srcL);
            nx = fmaf(m0, qx, nx); ny = fmaf(m0, qy, ny);
            qx = __shfl_sync(FULLMASK, Qx, srcL + 4);  qy = __shfl_sync(FULLMASK, Qy, srcL + 4);
            nx = fmaf(m1, qx, nx); ny = fmaf(m1, qy, ny);
            qx = __shfl_sync(FULLMASK, Qx, srcL + 8);  qy = __shfl_sync(FULLMASK, Qy, srcL + 8);
            nx = fmaf(m2, qx, nx); ny = fmaf(m2, qy, ny);
            qx = __shfl_sync(FULLMASK, Qx, srcL + 12); qy = __shfl_sync(FULLMASK, Qy, srcL + 12);
            nx = fmaf(m3, qx, nx); ny = fmaf(m3, qy, ny);
        }
        {   // remote half: l = 4(1-h) + cc
            float qx, qy;
            qx = __shfl_sync(FULLMASK, Qx, srcR);      qy = __shfl_sync(FULLMASK, Qy, srcR);
            nx = fmaf(o0, qx, nx); ny = fmaf(o0, qy, ny);
            qx = __shfl_sync(FULLMASK, Qx, srcR + 4);  qy = __shfl_sync(FULLMASK, Qy, srcR + 4);
            nx = fmaf(o1, qx, nx); ny = fmaf(o1, qy, ny);
            qx = __shfl_sync(FULLMASK, Qx, srcR + 8);  qy = __shfl_sync(FULLMASK, Qy, srcR + 8);
            nx = fmaf(o2, qx, nx); ny = fmaf(o2, qy, ny);
            qx = __shfl_sync(FULLMASK, Qx, srcR + 12); qy = __shfl_sync(FULLMASK, Qy, srcR + 12);
            nx = fmaf(o3, qx, nx); ny = fmaf(o3, qy, ny);
        }
        Qx = nx; Qy = ny;
        ++rcnt;
        if ((rcnt & 3) == 0 || rcnt == cnt) {
            float m = fmaxf(Qx, Qy);
            m = fmaxf(m, __shfl_xor_sync(FULLMASK, m, 1));
            m = fmaxf(m, __shfl_xor_sync(FULLMASK, m, 2));
            m = fmaxf(m, __shfl_xor_sync(FULLMASK, m, 4));
            m = fmaxf(m, __shfl_xor_sync(FULLMASK, m, 8));
            m = fmaxf(m, __shfl_xor_sync(FULLMASK, m, 16));
            float inv = rcpf(m);
            Qx *= inv; Qy *= inv;
        }
    };

    for (int u = 0; u + 2 <= cnt; u += 2) {
        float4 a = a4x; float bb = bix;
        if (u + 2 < cnt) { a4x = *ap; bix = *bp; ap += 16 * N_; bp += 8 * N_; }
        mstep(a, bb);
        a = a4y; bb = biy;
        if (u + 3 < cnt) { a4y = *ap; biy = *bp; ap += 16 * N_; bp += 8 * N_; }
        mstep(a, bb);
    }
    if (cnt & 1) mstep(a4x, bix);

    *(float2*)(g_Q + (size_t)(c * S_ + s) * 64 + lane * 2) = make_float2(Qx, Qy);
}

// ---------------------------------------------------------------------------
// pass2: sequential scan over segments. warp = (dir, chain).
// ---------------------------------------------------------------------------
__global__ void __launch_bounds__(128) pass2_kernel(
    const float* __restrict__ lb, const float* __restrict__ lz)
{
    const int w    = blockIdx.x * 4 + (threadIdx.x >> 5);
    const int lane = threadIdx.x & 31;
    const int q    = lane & 3;
    const int i    = lane >> 2;
    const bool is_bw = (w >= C_);
    const int c = is_bw ? w - C_ : w;
    const int b = c >> 6, n = c & 63;
    const int tile0 = b * TN + n;

    if (!is_bw) {
        float x = lz[n * 8 + i] + lb[tile0 * 8 + i];
        float m0 = x;
        m0 = fmaxf(m0, __shfl_xor_sync(FULLMASK, m0, 4));
        m0 = fmaxf(m0, __shfl_xor_sync(FULLMASK, m0, 8));
        m0 = fmaxf(m0, __shfl_xor_sync(FULLMASK, m0, 16));
        float vi = ex2f((x - m0) * L2E);       // v[i], replicated over q

        for (int s = 0; s <= 30; s++) {
            float2 Qr = *(const float2*)(g_Q + (size_t)(c * S_ + s) * 64 + lane * 2);
            float vx = __shfl_sync(FULLMASK, vi, 8 * q);
            float vy = __shfl_sync(FULLMASK, vi, 8 * q + 4);
            float p = fmaf(Qr.x, vx, Qr.y * vy);
            p += __shfl_xor_sync(FULLMASK, p, 1);
            p += __shfl_xor_sync(FULLMASK, p, 2);
            float m = p;
            m = fmaxf(m, __shfl_xor_sync(FULLMASK, m, 4));
            m = fmaxf(m, __shfl_xor_sync(FULLMASK, m, 8));
            m = fmaxf(m, __shfl_xor_sync(FULLMASK, m, 16));
            vi = p * rcpf(m);
            if (q == 0) g_Vb[(size_t)(c * S_ + s + 1) * 8 + i] = vi;
        }
    } else {
        float ri = 1.0f;
        for (int s = 31; s >= 1; s--) {
            float2 Qr = *(const float2*)(g_Q + (size_t)(c * S_ + s) * 64 + lane * 2);
            float pe = Qr.x * ri;
            float po = Qr.y * ri;
            pe += __shfl_xor_sync(FULLMASK, pe, 4);
            pe += __shfl_xor_sync(FULLMASK, pe, 8);
            pe += __shfl_xor_sync(FULLMASK, pe, 16);
            po += __shfl_xor_sync(FULLMASK, po, 4);
            po += __shfl_xor_sync(FULLMASK, po, 8);
            po += __shfl_xor_sync(FULLMASK, po, 16);
            float re = __shfl_sync(FULLMASK, pe, i >> 1);
            float ro = __shfl_sync(FULLMASK, po, i >> 1);
            float rn = (i & 1) ? ro : re;
            float m = fmaxf(pe, po);
            m = fmaxf(m, __shfl_xor_sync(FULLMASK, m, 1));
            m = fmaxf(m, __shfl_xor_sync(FULLMASK, m, 2));
            ri = rn * rcpf(m);
            if (q == 0) g_Rb[(size_t)(c * S_ + s) * 8 + i] = ri;
        }
    }
}

// ---------------------------------------------------------------------------
// pass3_fw: forward recursion per (chain,segment) -> g_fwu (unnormalized log2).
// lane (i=rr, ii) handles j-pair 2ii,2ii+1 of row i. Depth-2 prefetch.
// ---------------------------------------------------------------------------
__global__ void __launch_bounds__(128) pass3_fw_kernel(
    const float* __restrict__ la, const float* __restrict__ lb,
    const float* __restrict__ lz)
{
    const int w    = blockIdx.x * 4 + (threadIdx.x >> 5);
    const int lane = threadIdx.x & 31;
    const int ii   = lane & 3;
    const int rr   = lane >> 2;
    const int c = w >> 5, s = w & 31;
    const int b = c >> 6, n = c & 63;
    const int tile0 = b * TN + n;
    const int sel0 = ii * 8, sel1 = ii * 8 + 4;

    float prev;
    int t0;
    if (s == 0) {
        prev = (lz[n * 8 + rr] + lb[tile0 * 8 + rr]) * L2E;
        if (ii == 0) g_fwu[tile0 * 8 + rr] = prev;
        t0 = 1;
    } else {
        prev = lg2f(g_Vb[(c * S_ + s) * 8 + rr]);
        t0 = s * L_;
    }
    const int cnt = s * L_ + L_ - t0;        // 31 or 32

    const float2* ap = (const float2*)la + (tile0 + t0 * N_) * 32 + lane;
    const float*  bp = lb + (tile0 + t0 * N_) * 8 + rr;
    float*        op = g_fwu + (tile0 + t0 * N_) * 8 + rr;

    float2 avx = ap[0];       float bvx = bp[0];
    float2 avy = ap[32 * N_]; float bvy = bp[8 * N_];
    ap += 64 * N_; bp += 16 * N_;

    auto fstep = [&](float2 av, float bv) {
        float p0 = __shfl_sync(FULLMASK, prev, sel0);
        float p1 = __shfl_sync(FULLMASK, prev, sel1);
        float u0 = __shfl_sync(FULLMASK, prev, 0);
        float e = ex2f(fmaf(av.x, L2E, p0 - u0))
                + ex2f(fmaf(av.y, L2E, p1 - u0));
        e += __shfl_xor_sync(FULLMASK, e, 1);
        e += __shfl_xor_sync(FULLMASK, e, 2);
        float uu = fmaf(bv, L2E, lg2f(e));
        prev = uu;
        if (ii == 0) *op = uu;
        op += 8 * N_;
    };

    for (int u = 0; u + 2 <= cnt; u += 2) {
        float2 a = avx; float bb = bvx;
        if (u + 2 < cnt) { avx = *ap; bvx = *bp; ap += 32 * N_; bp += 8 * N_; }
        fstep(a, bb);
        a = avy; bb = bvy;
        if (u + 3 < cnt) { avy = *ap; bvy = *bp; ap += 32 * N_; bp += 8 * N_; }
        fstep(a, bb);
    }
    if (cnt & 1) fstep(avx, bvx);
}

// ---------------------------------------------------------------------------
// bwgamma: backward recursion + all output emission, ONE reduction per step.
// Warp = (chain, segment). lane (j=rr, ii) handles i-pair 2ii,2ii+1 of col j.
// Unified reduction; each ii-group stores its own output (0=bw,1=fw,2=g1);
// only gamma2's normalizer is fetched (lane|3). Depth-2 prefetch.
// ---------------------------------------------------------------------------
__global__ void __launch_bounds__(128) bwgamma_kernel(
    const float* __restrict__ la, const float* __restrict__ lb,
    float* __restrict__ fw, float* __restrict__ bwo,
    float* __restrict__ g1, float* __restrict__ g2)
{
    const int w    = blockIdx.x * 4 + (threadIdx.x >> 5);
    const int lane = threadIdx.x & 31;
    const int ii   = lane & 3;
    const int rr   = lane >> 2;
    const int c = w >> 5, s = w & 31;
    const int b = c >> 6, n = c & 63;
    const int tile0 = b * TN + n;
    const int sel0 = ii * 8, sel1 = ii * 8 + 4;
    const int lnZ  = lane | 3;              // same rr, ii=3 lane
    const int te = s * L_ + L_ - 1;
    const bool top = (s == 31);

    float prev  = top ? 0.0f : lg2f(g_Rb[(c * S_ + s + 1) * 8 + rr]);
    float fprev = g_fwu[(tile0 + te * N_) * 8 + rr];

    const float*  cp  = la + (size_t)(tile0 + te * N_) * 64 + ii * 16 + rr;
    const float2* bp2 = (const float2*)lb + (tile0 + te * N_) * 4 + ii;
    const float*  fp  = g_fwu + (tile0 + (te - 1) * N_) * 8 + rr;
    int ob  = (tile0 + te * N_) * 8 + rr;       // fw/bw/g1 (per-ii predication)
    int g2b = (tile0 + te * N_) * 64;           // gamma2 tile base

    // depth-2 prefetch (31 iterations always)
    float c0x = cp[0], c1x = cp[8];
    float2 bvx = bp2[0];
    float fcx = fp[0];
    float c0y = cp[-64 * N_], c1y = cp[-64 * N_ + 8];
    float2 bvy = bp2[-4 * N_];
    float fcy = fp[-8 * N_];
    cp -= 128 * N_; bp2 -= 8 * N_; fp -= 16 * N_;

    auto step = [&](float c0, float c1, float2 bv, float fcur, bool first) {
        // recursion core (beta_{t+1} -> beta_t)
        float p0 = __shfl_sync(FULLMASK, prev, sel0);
        float p1 = __shfl_sync(FULLMASK, prev, sel1);
        float u0 = __shfl_sync(FULLMASK, prev, 0);
        float a0 = fmaf(c0 + bv.x, L2E, p0 - u0);
        float a1 = fmaf(c1 + bv.y, L2E, p1 - u0);
        float e  = ex2f(a0) + ex2f(a1);
        e += __shfl_xor_sync(FULLMASK, e, 1);
        e += __shfl_xor_sync(FULLMASK, e, 2);   // e(rr) = sum over i

        // unified emission reduction for time t+1 (per-ii operand)
        float val = (ii == 0) ? prev
                  : (ii == 1) ? fprev
                  : (ii == 2) ? (fprev + prev) : fcur;
        float ee = ex2f(val);
        if (ii == 3) ee *= e;                   // gamma2 Z terms
        ee += __shfl_xor_sync(FULLMASK, ee, 4);
        ee += __shfl_xor_sync(FULLMASK, ee, 8);
        ee += __shfl_xor_sync(FULLMASK, ee, 16);
        float lgE = lg2f(ee);                   // per-ii normalizer
        float lgZ = __shfl_sync(FULLMASK, lgE, lnZ);

        // each ii-group stores its own output: same expression, own lgE
        float outv = (val - lgE) * LN2;
        if (ii == 0) bwo[ob] = (top && first) ? 0.0f : outv;
        else if (ii == 1) fw[ob] = outv;
        else if (ii == 2) g1[ob] = outv;

        float tt2 = (fcur - lgZ) * LN2;
        g2[g2b + 16 * ii + rr]     = fmaf(a0, LN2, tt2);
        g2[g2b + 16 * ii + 8 + rr] = fmaf(a1, LN2, tt2);

        prev  = lg2f(e);
        fprev = fcur;
        ob -= 8 * N_; g2b -= 64 * N_;
    };

    for (int u = 0; u + 2 <= 31; u += 2) {
        {
            float c0 = c0x, c1 = c1x; float2 bv = bvx; float fc = fcx;
            if (u + 2 < 31) {
                c0x = cp[0]; c1x = cp[8]; bvx = bp2[0]; fcx = fp[0];
                cp -= 64 * N_; bp2 -= 4 * N_; fp -= 8 * N_;
            }
            step(c0, c1, bv, fc, u == 0);
        }
        {
            float c0 = c0y, c1 = c1y; float2 bv = bvy; float fc = fcy;
            if (u + 3 < 31) {
                c0y = cp[0]; c1y = cp[8]; bvy = bp2[0]; fcy = fp[0];
                cp -= 64 * N_; bp2 -= 4 * N_; fp -= 8 * N_;
            }
            step(c0, c1, bv, fc, false);
        }
    }
    step(c0x, c1x, bvx, fcx, false);           // iteration 30 (odd leftover)

    // ---- tail emission for time t = s*L (prev = beta_{sL}, fprev = fwu[sL]) ----
    {
        float a0t = 0.f, a1t = 0.f, et = 1.0f, fct = 0.f;
        if (s != 0) {
            const float* cpe = la + (size_t)(tile0 + s * L_ * N_) * 64 + ii * 16 + rr;
            float  c0 = cpe[0];
            float  c1 = cpe[8];
            float2 bv = *((const float2*)lb + (tile0 + s * L_ * N_) * 4 + ii);
            fct = lg2f(g_Vb[(c * S_ + s) * 8 + rr]);     // fwu[sL-1] (shifted)
            float p0 = __shfl_sync(FULLMASK, prev, sel0);
            float p1 = __shfl_sync(FULLMASK, prev, sel1);
            float u0 = __shfl_sync(FULLMASK, prev, 0);
            a0t = fmaf(c0 + bv.x, L2E, p0 - u0);
            a1t = fmaf(c1 + bv.y, L2E, p1 - u0);
            et  = ex2f(a0t) + ex2f(a1t);
            et += __shfl_xor_sync(FULLMASK, et, 1);
            et += __shfl_xor_sync(FULLMASK, et, 2);
        }
        float val = (ii == 0) ? prev
                  : (ii == 1) ? fprev
                  : (ii == 2) ? (fprev + prev) : fct;
        float ee = ex2f(val);
        if (ii == 3) ee *= et;
        ee += __shfl_xor_sync(FULLMASK, ee, 4);
        ee += __shfl_xor_sync(FULLMASK, ee, 8);
        ee += __shfl_xor_sync(FULLMASK, ee, 16);
        float lgE = lg2f(ee);
        float lgZ = __shfl_sync(FULLMASK, lgE, lnZ);

        float outv = (val - lgE) * LN2;
        if (ii == 0) bwo[ob] = outv;
        else if (ii == 1) fw[ob] = outv;
        else if (ii == 2) g1[ob] = outv;

        if (s == 0) {                            // gamma2[0] = zeros
            g2[g2b + 16 * ii + rr]     = 0.0f;
            g2[g2b + 16 * ii + 8 + rr] = 0.0f;
        } else {
            float tt2 = (fct - lgZ) * LN2;
            g2[g2b + 16 * ii + rr]     = fmaf(a0t, LN2, tt2);
            g2[g2b + 16 * ii + 8 + rr] = fmaf(a1t, LN2, tt2);
        }
    }
}

extern "C" void kernel_launch(void* const* d_in, const int* in_sizes, int n_in,
                              void* d_out, int out_size) {
    const float* la = (const float*)d_in[0];   // log_a  (B,T,N,K,K)
    const float* lb = (const float*)d_in[1];   // log_b  (B,T,N,K)
    const float* lz = (const float*)d_in[2];   // logprob_z1 (N,K)

    float* out = (float*)d_out;
    float* fw = out;
    float* bw = fw + BTNK;
    float* g1 = bw + BTNK;
    float* g2 = g1 + BTNK;

    pass1_kernel<<<(C_ * S_) / 4, 128>>>(la, lb);          // 16384 warps
    pass2_kernel<<<(2 * C_) / 4, 128>>>(lb, lz);           // 1024 warps
    pass3_fw_kernel<<<(C_ * S_) / 4, 128>>>(la, lb, lz);   // 16384 warps
    bwgamma_kernel<<<(C_ * S_) / 4, 128>>>(la, lb, fw, bw, g1, g2);
}

// round 12
// speedup vs baseline: 1.3240x; 1.1249x over previous
#include <cuda_runtime.h>

// RSLDS forward-backward smoother, B=8 T=1024 N=64 K=8.
// Outputs: forward | backward | gamma1 | gamma2 (concatenated in d_out).
//
// Blocked scan:
//   pass1: per-(chain,segment) 8x8 transfer-matrix products (linear)
//   pass2: sequential scan over segments -> boundary vectors (g_Vb, g_Rb)
//   fwbwgamma (R12): per-(chain,segment) FORWARD recursion cached in SMEM
//          (1KB/warp), then BACKWARD recursion + all posterior emission in the
//          same warp. Eliminates g_fwu round-trip; backward la reads hit L1/L2
//          (same 8KB the warp just streamed forward).

#define FULLMASK 0xffffffffu
constexpr int B_ = 8, T_ = 1024, N_ = 64, K_ = 8;
constexpr int C_ = B_ * N_;          // 512 chains
constexpr int L_ = 32, S_ = 32;      // segment length, count
constexpr int TN = T_ * N_;
constexpr long long BTNK = (long long)B_ * T_ * N_ * K_;

__device__ float g_Q  [C_ * S_ * 64];  // segment transfer matrices (linear)
__device__ float g_Vb [C_ * S_ * 8];   // fw boundaries (linear, rescaled)
__device__ float g_Rb [C_ * S_ * 8];   // bw boundaries (linear, rescaled)

__device__ __forceinline__ float ex2f(float x) {
    float y; asm("ex2.approx.ftz.f32 %0, %1;" : "=f"(y) : "f"(x)); return y;
}
__device__ __forceinline__ float lg2f(float x) {
    float y; asm("lg2.approx.f32 %0, %1;" : "=f"(y) : "f"(x)); return y;
}
__device__ __forceinline__ float rcpf(float x) {
    float y; asm("rcp.approx.ftz.f32 %0, %1;" : "=f"(y) : "f"(x)); return y;
}

#define L2E 1.4426950408889634f
#define LN2 0.6931471805599453f

// ---------------------------------------------------------------------------
// pass1: Q_s = M_te ... M_ts,  M_t[i,j] = exp(log_b_t[i] + log_a_t[i,j]).
// lane (i = lane>>2, q = lane&3) holds Q[i,2q], Q[i,2q+1].
// Lane loads M row-half [4h..4h+4) with h = q>>1; butterfly xor 2 for the rest.
// ---------------------------------------------------------------------------
__global__ void __launch_bounds__(128) pass1_kernel(
    const float* __restrict__ la, const float* __restrict__ lb)
{
    const int w    = blockIdx.x * 4 + (threadIdx.x >> 5);
    const int lane = threadIdx.x & 31;
    const int q    = lane & 3;
    const int i    = lane >> 2;
    const int h    = q >> 1;
    const int c = w >> 5, s = w & 31;
    const int b = c >> 6, n = c & 63;
    const int tile0 = b * TN + n;

    const int srcL = 16 * h + q;          // Q-gather lanes for local half
    const int srcR = 16 - 16 * h + q;     // and remote half

    const int ts = (s == 0) ? 1 : s * L_;
    const int te = s * L_ + L_ - 1;
    const int cnt = te - ts;              // multiply steps: 30 or 31

    const float4* ap = (const float4*)(la + (size_t)(tile0 + ts * N_) * 64) + i * 2 + h;
    const float*  bp = lb + (tile0 + ts * N_) * 8 + i;

    float Qx, Qy;
    {   // Q = M_ts
        float4 a4 = *ap;
        float  biL = (*bp) * L2E;
        float ax = (q & 1) ? a4.z : a4.x;
        float ay = (q & 1) ? a4.w : a4.y;
        Qx = ex2f(fmaf(ax, L2E, biL));
        Qy = ex2f(fmaf(ay, L2E, biL));
        ap += 16 * N_; bp += 8 * N_;
    }

    // depth-2 prefetch buffers (cnt >= 30 always)
    float4 a4x = ap[0];        float bix = bp[0];
    float4 a4y = ap[16 * N_];  float biy = bp[8 * N_];
    ap += 32 * N_; bp += 16 * N_;

    int rcnt = 0;
    auto mstep = [&](float4 a4, float bi) {
        float biL = bi * L2E;
        float m0 = ex2f(fmaf(a4.x, L2E, biL));
        float m1 = ex2f(fmaf(a4.y, L2E, biL));
        float m2 = ex2f(fmaf(a4.z, L2E, biL));
        float m3 = ex2f(fmaf(a4.w, L2E, biL));
        float o0 = __shfl_xor_sync(FULLMASK, m0, 2);
        float o1 = __shfl_xor_sync(FULLMASK, m1, 2);
        float o2 = __shfl_xor_sync(FULLMASK, m2, 2);
        float o3 = __shfl_xor_sync(FULLMASK, m3, 2);

        float nx = 0.f, ny = 0.f;
        {   // local half: l = 4h + cc
            float qx, qy;
            qx = __shfl_sync(FULLMASK, Qx, srcL);      qy = __shfl_sync(FULLMASK, Qy, srcL);
            nx = fmaf(m0, qx, nx); ny = fmaf(m0, qy, ny);
            qx = __shfl_sync(FULLMASK, Qx, srcL + 4);  qy = __shfl_sync(FULLMASK, Qy, srcL + 4);
            nx = fmaf(m1, qx, nx); ny = fmaf(m1, qy, ny);
            qx = __shfl_sync(FULLMASK, Qx, srcL + 8);  qy = __shfl_sync(FULLMASK, Qy, srcL + 8);
            nx = fmaf(m2, qx, nx); ny = fmaf(m2, qy, ny);
            qx = __shfl_sync(FULLMASK, Qx, srcL + 12); qy = __shfl_sync(FULLMASK, Qy, srcL + 12);
            nx = fmaf(m3, qx, nx); ny = fmaf(m3, qy, ny);
        }
        {   // remote half: l = 4(1-h) + cc
            float qx, qy;
            qx = __shfl_sync(FULLMASK, Qx, srcR);      qy = __shfl_sync(FULLMASK, Qy, srcR);
            nx = fmaf(o0, qx, nx); ny = fmaf(o0, qy, ny);
            qx = __shfl_sync(FULLMASK, Qx, srcR + 4);  qy = __shfl_sync(FULLMASK, Qy, srcR + 4);
            nx = fmaf(o1, qx, nx); ny = fmaf(o1, qy, ny);
            qx = __shfl_sync(FULLMASK, Qx, srcR + 8);  qy = __shfl_sync(FULLMASK, Qy, srcR + 8);
            nx = fmaf(o2, qx, nx); ny = fmaf(o2, qy, ny);
            qx = __shfl_sync(FULLMASK, Qx, srcR + 12); qy = __shfl_sync(FULLMASK, Qy, srcR + 12);
            nx = fmaf(o3, qx, nx); ny = fmaf(o3, qy, ny);
        }
        Qx = nx; Qy = ny;
        ++rcnt;
        if ((rcnt & 3) == 0 || rcnt == cnt) {
            float m = fmaxf(Qx, Qy);
            m = fmaxf(m, __shfl_xor_sync(FULLMASK, m, 1));
            m = fmaxf(m, __shfl_xor_sync(FULLMASK, m, 2));
            m = fmaxf(m, __shfl_xor_sync(FULLMASK, m, 4));
            m = fmaxf(m, __shfl_xor_sync(FULLMASK, m, 8));
            m = fmaxf(m, __shfl_xor_sync(FULLMASK, m, 16));
            float inv = rcpf(m);
            Qx *= inv; Qy *= inv;
        }
    };

    for (int u = 0; u + 2 <= cnt; u += 2) {
        float4 a = a4x; float bb = bix;
        if (u + 2 < cnt) { a4x = *ap; bix = *bp; ap += 16 * N_; bp += 8 * N_; }
        mstep(a, bb);
        a = a4y; bb = biy;
        if (u + 3 < cnt) { a4y = *ap; biy = *bp; ap += 16 * N_; bp += 8 * N_; }
        mstep(a, bb);
    }
    if (cnt & 1) mstep(a4x, bix);

    *(float2*)(g_Q + (size_t)(c * S_ + s) * 64 + lane * 2) = make_float2(Qx, Qy);
}

// ---------------------------------------------------------------------------
// pass2: sequential scan over segments. warp = (dir, chain).
// ---------------------------------------------------------------------------
__global__ void __launch_bounds__(128) pass2_kernel(
    const float* __restrict__ lb, const float* __restrict__ lz)
{
    const int w    = blockIdx.x * 4 + (threadIdx.x >> 5);
    const int lane = threadIdx.x & 31;
    const int q    = lane & 3;
    const int i    = lane >> 2;
    const bool is_bw = (w >= C_);
    const int c = is_bw ? w - C_ : w;
    const int b = c >> 6, n = c & 63;
    const int tile0 = b * TN + n;

    if (!is_bw) {
        float x = lz[n * 8 + i] + lb[tile0 * 8 + i];
        float m0 = x;
        m0 = fmaxf(m0, __shfl_xor_sync(FULLMASK, m0, 4));
        m0 = fmaxf(m0, __shfl_xor_sync(FULLMASK, m0, 8));
        m0 = fmaxf(m0, __shfl_xor_sync(FULLMASK, m0, 16));
        float vi = ex2f((x - m0) * L2E);       // v[i], replicated over q

        for (int s = 0; s <= 30; s++) {
            float2 Qr = *(const float2*)(g_Q + (size_t)(c * S_ + s) * 64 + lane * 2);
            float vx = __shfl_sync(FULLMASK, vi, 8 * q);
            float vy = __shfl_sync(FULLMASK, vi, 8 * q + 4);
            float p = fmaf(Qr.x, vx, Qr.y * vy);
            p += __shfl_xor_sync(FULLMASK, p, 1);
            p += __shfl_xor_sync(FULLMASK, p, 2);
            float m = p;
            m = fmaxf(m, __shfl_xor_sync(FULLMASK, m, 4));
            m = fmaxf(m, __shfl_xor_sync(FULLMASK, m, 8));
            m = fmaxf(m, __shfl_xor_sync(FULLMASK, m, 16));
            vi = p * rcpf(m);
            if (q == 0) g_Vb[(size_t)(c * S_ + s + 1) * 8 + i] = vi;
        }
    } else {
        float ri = 1.0f;
        for (int s = 31; s >= 1; s--) {
            float2 Qr = *(const float2*)(g_Q + (size_t)(c * S_ + s) * 64 + lane * 2);
            float pe = Qr.x * ri;
            float po = Qr.y * ri;
            pe += __shfl_xor_sync(FULLMASK, pe, 4);
            pe += __shfl_xor_sync(FULLMASK, pe, 8);
            pe += __shfl_xor_sync(FULLMASK, pe, 16);
            po += __shfl_xor_sync(FULLMASK, po, 4);
            po += __shfl_xor_sync(FULLMASK, po, 8);
            po += __shfl_xor_sync(FULLMASK, po, 16);
            float re = __shfl_sync(FULLMASK, pe, i >> 1);
            float ro = __shfl_sync(FULLMASK, po, i >> 1);
            float rn = (i & 1) ? ro : re;
            float m = fmaxf(pe, po);
            m = fmaxf(m, __shfl_xor_sync(FULLMASK, m, 1));
            m = fmaxf(m, __shfl_xor_sync(FULLMASK, m, 2));
            ri = rn * rcpf(m);
            if (q == 0) g_Rb[(size_t)(c * S_ + s) * 8 + i] = ri;
        }
    }
}

// ---------------------------------------------------------------------------
// fwbwgamma: forward recursion (alphas cached in SMEM, 1KB/warp), then
// backward recursion + all output emission in the same warp.
// fw sweep: lane (i=rr, ii) handles j-pair 2ii,2ii+1 of row i.
// bw sweep: lane (j=rr, ii) handles i-pair 2ii,2ii+1 of col j; unified per-ii
// reduction; each ii-group stores its own output (0=bw,1=fw,2=g1).
// ---------------------------------------------------------------------------
__global__ void __launch_bounds__(128) fwbwgamma_kernel(
    const float* __restrict__ la, const float* __restrict__ lb,
    const float* __restrict__ lz,
    float* __restrict__ fw, float* __restrict__ bwo,
    float* __restrict__ g1, float* __restrict__ g2)
{
    __shared__ float sfw[4 * 264];          // 264-stride staggers banks per warp
    const int wl   = threadIdx.x >> 5;
    const int w    = blockIdx.x * 4 + wl;
    const int lane = threadIdx.x & 31;
    const int ii   = lane & 3;
    const int rr   = lane >> 2;
    const int c = w >> 5, s = w & 31;
    const int b = c >> 6, n = c & 63;
    const int tile0 = b * TN + n;
    const int sel0 = ii * 8, sel1 = ii * 8 + 4;
    const int sL = s * L_;
    const int te = sL + L_ - 1;
    float* fc = sfw + wl * 264;             // fwu cache: [tloc][rr], tloc = t-sL

    // ===================== forward sweep =====================
    {
        float prev;
        int t0;
        if (s == 0) {
            prev = (lz[n * 8 + rr] + lb[tile0 * 8 + rr]) * L2E;
            if (ii == 0) fc[rr] = prev;     // tloc 0
            t0 = 1;
        } else {
            prev = lg2f(g_Vb[(c * S_ + s) * 8 + rr]);
            t0 = sL;
        }
        const int cnt = te - t0 + 1;        // 31 or 32

        const float2* ap = (const float2*)la + (tile0 + t0 * N_) * 32 + lane;
        const float*  bp = lb + (tile0 + t0 * N_) * 8 + rr;
        float*        op = fc + (t0 - sL) * 8 + rr;

        float2 avx = ap[0];       float bvx = bp[0];
        float2 avy = ap[32 * N_]; float bvy = bp[8 * N_];
        ap += 64 * N_; bp += 16 * N_;

        auto fstep = [&](float2 av, float bv) {
            float p0 = __shfl_sync(FULLMASK, prev, sel0);
            float p1 = __shfl_sync(FULLMASK, prev, sel1);
            float u0 = __shfl_sync(FULLMASK, prev, 0);
            float e = ex2f(fmaf(av.x, L2E, p0 - u0))
                    + ex2f(fmaf(av.y, L2E, p1 - u0));
            e += __shfl_xor_sync(FULLMASK, e, 1);
            e += __shfl_xor_sync(FULLMASK, e, 2);
            float uu = fmaf(bv, L2E, lg2f(e));
            prev = uu;
            if (ii == 0) *op = uu;
            op += 8;
        };

        for (int u = 0; u + 2 <= cnt; u += 2) {
            float2 a = avx; float bb = bvx;
            if (u + 2 < cnt) { avx = *ap; bvx = *bp; ap += 32 * N_; bp += 8 * N_; }
            fstep(a, bb);
            a = avy; bb = bvy;
            if (u + 3 < cnt) { avy = *ap; bvy = *bp; ap += 32 * N_; bp += 8 * N_; }
            fstep(a, bb);
        }
        if (cnt & 1) fstep(avx, bvx);
    }
    __syncwarp();

    // ===================== backward + emission sweep =====================
    const int lnZ = lane | 3;               // same rr, ii=3 lane
    const bool top = (s == 31);

    float prev  = top ? 0.0f : lg2f(g_Rb[(c * S_ + s + 1) * 8 + rr]);
    float fprev = fc[31 * 8 + rr];          // fwu[te]

    const float*  cp  = la + (size_t)(tile0 + te * N_) * 64 + ii * 16 + rr;
    const float2* bp2 = (const float2*)lb + (tile0 + te * N_) * 4 + ii;
    const float*  fp  = fc + 30 * 8 + rr;   // fwu[te-1]
    int ob  = (tile0 + te * N_) * 8 + rr;   // fw/bw/g1 (per-ii predication)
    int g2b = (tile0 + te * N_) * 64;       // gamma2 tile base

    // depth-2 prefetch (31 iterations always)
    float c0x = cp[0], c1x = cp[8];
    float2 bvx = bp2[0];
    float fcx = fp[0];
    float c0y = cp[-64 * N_], c1y = cp[-64 * N_ + 8];
    float2 bvy = bp2[-4 * N_];
    float fcy = fp[-8];
    cp -= 128 * N_; bp2 -= 8 * N_; fp -= 16;

    auto step = [&](float c0, float c1, float2 bv, float fcur, bool first) {
        // recursion core (beta_{t+1} -> beta_t)
        float p0 = __shfl_sync(FULLMASK, prev, sel0);
        float p1 = __shfl_sync(FULLMASK, prev, sel1);
        float u0 = __shfl_sync(FULLMASK, prev, 0);
        float a0 = fmaf(c0 + bv.x, L2E, p0 - u0);
        float a1 = fmaf(c1 + bv.y, L2E, p1 - u0);
        float e  = ex2f(a0) + ex2f(a1);
        e += __shfl_xor_sync(FULLMASK, e, 1);
        e += __shfl_xor_sync(FULLMASK, e, 2);   // e(rr) = sum over i

        // unified emission reduction for time t+1 (per-ii operand)
        float val = (ii == 0) ? prev
                  : (ii == 1) ? fprev
                  : (ii == 2) ? (fprev + prev) : fcur;
        float ee = ex2f(val);
        if (ii == 3) ee *= e;                   // gamma2 Z terms
        ee += __shfl_xor_sync(FULLMASK, ee, 4);
        ee += __shfl_xor_sync(FULLMASK, ee, 8);
        ee += __shfl_xor_sync(FULLMASK, ee, 16);
        float lgE = lg2f(ee);                   // per-ii normalizer
        float lgZ = __shfl_sync(FULLMASK, lgE, lnZ);

        float outv = (val - lgE) * LN2;
        if (ii == 0) bwo[ob] = (top && first) ? 0.0f : outv;
        else if (ii == 1) fw[ob] = outv;
        else if (ii == 2) g1[ob] = outv;

        float tt2 = (fcur - lgZ) * LN2;
        g2[g2b + 16 * ii + rr]     = fmaf(a0, LN2, tt2);
        g2[g2b + 16 * ii + 8 + rr] = fmaf(a1, LN2, tt2);

        prev  = lg2f(e);
        fprev = fcur;
        ob -= 8 * N_; g2b -= 64 * N_;
    };

    for (int u = 0; u + 2 <= 31; u += 2) {
        {
            float c0 = c0x, c1 = c1x; float2 bv = bvx; float fcv = fcx;
            if (u + 2 < 31) {
                c0x = cp[0]; c1x = cp[8]; bvx = bp2[0]; fcx = fp[0];
                cp -= 64 * N_; bp2 -= 4 * N_; fp -= 8;
            }
            step(c0, c1, bv, fcv, u == 0);
        }
        {
            float c0 = c0y, c1 = c1y; float2 bv = bvy; float fcv = fcy;
            if (u + 3 < 31) {
                c0y = cp[0]; c1y = cp[8]; bvy = bp2[0]; fcy = fp[0];
                cp -= 64 * N_; bp2 -= 4 * N_; fp -= 8;
            }
            step(c0, c1, bv, fcv, false);
        }
    }
    step(c0x, c1x, bvx, fcx, false);           // iteration 30 (odd leftover)

    // ---- tail emission for time t = sL (prev = beta_{sL}, fprev = fwu[sL]) ----
    {
        float a0t = 0.f, a1t = 0.f, et = 1.0f, fct = 0.f;
        if (s != 0) {
            const float* cpe = la + (size_t)(tile0 + sL * N_) * 64 + ii * 16 + rr;
            float  c0 = cpe[0];
            float  c1 = cpe[8];
            float2 bv = *((const float2*)lb + (tile0 + sL * N_) * 4 + ii);
            fct = lg2f(g_Vb[(c * S_ + s) * 8 + rr]);     // fwu[sL-1] (shifted)
            float p0 = __shfl_sync(FULLMASK, prev, sel0);
            float p1 = __shfl_sync(FULLMASK, prev, sel1);
            float u0 = __shfl_sync(FULLMASK, prev, 0);
            a0t = fmaf(c0 + bv.x, L2E, p0 - u0);
            a1t = fmaf(c1 + bv.y, L2E, p1 - u0);
            et  = ex2f(a0t) + ex2f(a1t);
            et += __shfl_xor_sync(FULLMASK, et, 1);
            et += __shfl_xor_sync(FULLMASK, et, 2);
        }
        float val = (ii == 0) ? prev
                  : (ii == 1) ? fprev
                  : (ii == 2) ? (fprev + prev) : fct;
        float ee = ex2f(val);
        if (ii == 3) ee *= et;
        ee += __shfl_xor_sync(FULLMASK, ee, 4);
        ee += __shfl_xor_sync(FULLMASK, ee, 8);
        ee += __shfl_xor_sync(FULLMASK, ee, 16);
        float lgE = lg2f(ee);
        float lgZ = __shfl_sync(FULLMASK, lgE, lnZ);

        float outv = (val - lgE) * LN2;
        if (ii == 0) bwo[ob] = outv;
        else if (ii == 1) fw[ob] = outv;
        else if (ii == 2) g1[ob] = outv;

        if (s == 0) {                            // gamma2[0] = zeros
            g2[g2b + 16 * ii + rr]     = 0.0f;
            g2[g2b + 16 * ii + 8 + rr] = 0.0f;
        } else {
            float tt2 = (fct - lgZ) * LN2;
            g2[g2b + 16 * ii + rr]     = fmaf(a0t, LN2, tt2);
            g2[g2b + 16 * ii + 8 + rr] = fmaf(a1t, LN2, tt2);
        }
    }
}

extern "C" void kernel_launch(void* const* d_in, const int* in_sizes, int n_in,
                              void* d_out, int out_size) {
    const float* la = (const float*)d_in[0];   // log_a  (B,T,N,K,K)
    const float* lb = (const float*)d_in[1];   // log_b  (B,T,N,K)
    const float* lz = (const float*)d_in[2];   // logprob_z1 (N,K)

    float* out = (float*)d_out;
    float* fw = out;
    float* bw = fw + BTNK;
    float* g1 = bw + BTNK;
    float* g2 = g1 + BTNK;

    pass1_kernel<<<(C_ * S_) / 4, 128>>>(la, lb);              // 16384 warps
    pass2_kernel<<<(2 * C_) / 4, 128>>>(lb, lz);               // 1024 warps
    fwbwgamma_kernel<<<(C_ * S_) / 4, 128>>>(la, lb, lz, fw, bw, g1, g2);
}